// round 11
// baseline (speedup 1.0000x reference)
#include <cuda_runtime.h>
#include <mma.h>
#include <cuda_fp16.h>
#include <math.h>
#include <stdint.h>

using namespace nvcuda;

#define D_MODEL 1024
#define VOCAB   32000
#define BB      2
#define TT      2048
#define M_TOT   (BB * TT)      // 4096
#define D_FF    (4 * D_MODEL)  // 4096

// ---------------------------------------------------------------------------
// Scratch
// ---------------------------------------------------------------------------
__device__ float  g_x [M_TOT * D_MODEL];
__device__ __half g_xh[M_TOT * D_MODEL];
__device__ __half g_q [M_TOT * D_MODEL];   // q pre-scaled by 1/32
__device__ __half g_k [M_TOT * D_MODEL];
__device__ __half g_v [M_TOT * D_MODEL];
__device__ float  g_s [BB * TT * TT];
__device__ __half g_p [BB * TT * TT];
__device__ __half g_h [M_TOT * D_FF];
__device__ __half g_wq[D_MODEL * D_MODEL];
__device__ __half g_wk[D_MODEL * D_MODEL];
__device__ __half g_wv[D_MODEL * D_MODEL];
__device__ __half g_w1[D_MODEL * D_FF];
__device__ __half g_w2[D_FF * D_MODEL];
__device__ __half g_wo[D_MODEL * VOCAB];

// ---------------------------------------------------------------------------
// helpers
// ---------------------------------------------------------------------------
__device__ __forceinline__ void cp_async16(void* dst, const void* src) {
    unsigned d = (unsigned)__cvta_generic_to_shared(dst);
    asm volatile("cp.async.ca.shared.global [%0], [%1], 16;\n" :: "r"(d), "l"(src));
}
__device__ __forceinline__ void cp_commit() { asm volatile("cp.async.commit_group;\n"); }
__device__ __forceinline__ void cp_wait1()  { asm volatile("cp.async.wait_group 1;\n"); }

__global__ void f2h_kernel(const float* __restrict__ in, __half* __restrict__ out, int n8) {
    int i = blockIdx.x * blockDim.x + threadIdx.x;
    if (i >= n8) return;
    const float4 a = reinterpret_cast<const float4*>(in)[i * 2 + 0];
    const float4 b = reinterpret_cast<const float4*>(in)[i * 2 + 1];
    __half2 h0 = __floats2half2_rn(a.x, a.y);
    __half2 h1 = __floats2half2_rn(a.z, a.w);
    __half2 h2 = __floats2half2_rn(b.x, b.y);
    __half2 h3 = __floats2half2_rn(b.z, b.w);
    uint4 pk;
    pk.x = *reinterpret_cast<unsigned*>(&h0);
    pk.y = *reinterpret_cast<unsigned*>(&h1);
    pk.z = *reinterpret_cast<unsigned*>(&h2);
    pk.w = *reinterpret_cast<unsigned*>(&h3);
    reinterpret_cast<uint4*>(out)[i] = pk;
}

__global__ void embed_kernel(const int* __restrict__ idx,
                             const float* __restrict__ tok,
                             const float* __restrict__ pos) {
    int i = blockIdx.x * blockDim.x + threadIdx.x;
    int n4 = (M_TOT * D_MODEL) / 4;
    if (i >= n4) return;
    int e   = i * 4;
    int row = e / D_MODEL;
    int d   = e % D_MODEL;
    int t   = row % TT;
    int tk  = idx[row];
    const float4 a = *reinterpret_cast<const float4*>(tok + (long)tk * D_MODEL + d);
    const float4 b = *reinterpret_cast<const float4*>(pos + (long)t  * D_MODEL + d);
    float4 o;
    o.x = a.x + b.x; o.y = a.y + b.y; o.z = a.z + b.z; o.w = a.w + b.w;
    *reinterpret_cast<float4*>(g_x + e) = o;
    __half2 h0 = __floats2half2_rn(o.x, o.y);
    __half2 h1 = __floats2half2_rn(o.z, o.w);
    uint2 pk;
    pk.x = *reinterpret_cast<unsigned*>(&h0);
    pk.y = *reinterpret_cast<unsigned*>(&h1);
    *reinterpret_cast<uint2*>(g_xh + e) = pk;
}

// ===========================================================================
// Kernel A (R9-proven): 128x128x64, 256 thr, 8 warps 64x32, 2 CTAs/SM.
// ===========================================================================
template<bool TRANSB, bool HAS_BIAS, bool DO_GELU, bool HAS_RES,
         bool CAUSAL, bool KCAP, bool OUT_F32, bool OUT_HALF>
__global__ __launch_bounds__(256, 2)
void hgemm(const __half* __restrict__ A, const __half* __restrict__ Bm,
           const float* __restrict__ bias, const float* __restrict__ Res,
           float* __restrict__ C, __half* __restrict__ C2,
           int M, int N, int K,
           float alpha, float res_scale,
           long sA, long sB, long sC, long sR)
{
    constexpr int BM = 128, BN = 128, BK = 64;
    constexpr int LDA   = 72;
    constexpr int LDB   = TRANSB ? 72 : 136;
    constexpr int BROWS = TRANSB ? BM : BK;

    if (CAUSAL && blockIdx.x > blockIdx.y) return;

    A  += (long)blockIdx.z * sA;
    Bm += (long)blockIdx.z * sB;
    if (OUT_F32)  C  += (long)blockIdx.z * sC;
    if (OUT_HALF) C2 += (long)blockIdx.z * sC;
    if (HAS_RES)  Res += (long)blockIdx.z * sR;

    __shared__ __half As[2][BM][LDA];
    __shared__ __half Bs[2][BROWS][LDB];
    __shared__ float  stg[8][16][20];

    const int tid  = threadIdx.x;
    const int wid  = tid / 32;
    const int lane = tid % 32;
    const int warp_m = wid % 2;
    const int warp_n = wid / 2;
    const int cRow = blockIdx.y * BM;
    const int cCol = blockIdx.x * BN;

    const int Keff = KCAP ? (K < cRow + BM ? K : cRow + BM) : K;
    const int nT = Keff / BK;

    const int a_r0 = tid >> 3;
    const int a_c  = (tid & 7) * 8;
    const int b_r0 = tid >> 4;
    const int b_c  = (tid & 15) * 8;

    const __half* Abase = A + (long)cRow * K + a_c;

    {
#pragma unroll
        for (int i = 0; i < 4; i++)
            cp_async16(&As[0][a_r0 + 32 * i][a_c], Abase + (long)(a_r0 + 32 * i) * K);
        if (!TRANSB) {
#pragma unroll
            for (int i = 0; i < 4; i++)
                cp_async16(&Bs[0][b_r0 + 16 * i][b_c], Bm + (long)(b_r0 + 16 * i) * N + cCol + b_c);
        } else {
#pragma unroll
            for (int i = 0; i < 4; i++)
                cp_async16(&Bs[0][a_r0 + 32 * i][a_c], Bm + (long)(cCol + a_r0 + 32 * i) * K + a_c);
        }
        cp_commit();
    }

    wmma::fragment<wmma::accumulator, 16, 16, 16, float> acc[4][2];
#pragma unroll
    for (int mt = 0; mt < 4; mt++)
#pragma unroll
        for (int nt = 0; nt < 2; nt++)
            wmma::fill_fragment(acc[mt][nt], 0.0f);

    for (int t = 0; t < nT; t++) {
        if (t + 1 < nT) {
            const int kt = (t + 1) * BK;
            const int nb = (t + 1) & 1;
#pragma unroll
            for (int i = 0; i < 4; i++)
                cp_async16(&As[nb][a_r0 + 32 * i][a_c], Abase + kt + (long)(a_r0 + 32 * i) * K);
            if (!TRANSB) {
#pragma unroll
                for (int i = 0; i < 4; i++)
                    cp_async16(&Bs[nb][b_r0 + 16 * i][b_c], Bm + (long)(kt + b_r0 + 16 * i) * N + cCol + b_c);
            } else {
#pragma unroll
                for (int i = 0; i < 4; i++)
                    cp_async16(&Bs[nb][a_r0 + 32 * i][a_c], Bm + (long)(cCol + a_r0 + 32 * i) * K + kt + a_c);
            }
        }
        cp_commit();
        cp_wait1();
        __syncthreads();

        const int cb = t & 1;
#pragma unroll
        for (int kk = 0; kk < BK; kk += 16) {
            wmma::fragment<wmma::matrix_a, 16, 16, 16, __half, wmma::row_major> af[4];
#pragma unroll
            for (int mt = 0; mt < 4; mt++)
                wmma::load_matrix_sync(af[mt], &As[cb][warp_m * 64 + mt * 16][kk], LDA);
            if (!TRANSB) {
                wmma::fragment<wmma::matrix_b, 16, 16, 16, __half, wmma::row_major> bf[2];
#pragma unroll
                for (int nt = 0; nt < 2; nt++)
                    wmma::load_matrix_sync(bf[nt], &Bs[cb][kk][warp_n * 32 + nt * 16], LDB);
#pragma unroll
                for (int mt = 0; mt < 4; mt++)
#pragma unroll
                    for (int nt = 0; nt < 2; nt++)
                        wmma::mma_sync(acc[mt][nt], af[mt], bf[nt], acc[mt][nt]);
            } else {
                wmma::fragment<wmma::matrix_b, 16, 16, 16, __half, wmma::col_major> bf[2];
#pragma unroll
                for (int nt = 0; nt < 2; nt++)
                    wmma::load_matrix_sync(bf[nt], &Bs[cb][warp_n * 32 + nt * 16][kk], LDB);
#pragma unroll
                for (int mt = 0; mt < 4; mt++)
#pragma unroll
                    for (int nt = 0; nt < 2; nt++)
                        wmma::mma_sync(acc[mt][nt], af[mt], bf[nt], acc[mt][nt]);
            }
        }
        __syncthreads();
    }

    const int er  = lane >> 1;
    const int ec0 = (lane & 1) * 8;
#pragma unroll
    for (int mt = 0; mt < 4; mt++) {
#pragma unroll
        for (int nt = 0; nt < 2; nt++) {
            wmma::store_matrix_sync(&stg[wid][0][0], acc[mt][nt], 20, wmma::mem_row_major);
            __syncwarp();
            long grow = cRow + warp_m * 64 + mt * 16 + er;
            long gcol = cCol + warp_n * 32 + nt * 16 + ec0;
            float fv[8];
#pragma unroll
            for (int j = 0; j < 8; j++) {
                float v = alpha * stg[wid][er][ec0 + j];
                if (HAS_BIAS) v += bias[gcol + j];
                if (DO_GELU)  v = 0.5f * v * (1.0f + erff(v * 0.70710678118f));
                if (HAS_RES)  v = Res[grow * N + gcol + j] + res_scale * v;
                fv[j] = v;
            }
            if (OUT_F32) {
                float4 v0 = { fv[0], fv[1], fv[2], fv[3] };
                float4 v1 = { fv[4], fv[5], fv[6], fv[7] };
                *reinterpret_cast<float4*>(C + grow * N + gcol)     = v0;
                *reinterpret_cast<float4*>(C + grow * N + gcol + 4) = v1;
            }
            if (OUT_HALF) {
                __half2 h0 = __floats2half2_rn(fv[0], fv[1]);
                __half2 h1 = __floats2half2_rn(fv[2], fv[3]);
                __half2 h2 = __floats2half2_rn(fv[4], fv[5]);
                __half2 h3 = __floats2half2_rn(fv[6], fv[7]);
                uint4 pk;
                pk.x = *reinterpret_cast<unsigned*>(&h0);
                pk.y = *reinterpret_cast<unsigned*>(&h1);
                pk.z = *reinterpret_cast<unsigned*>(&h2);
                pk.w = *reinterpret_cast<unsigned*>(&h3);
                *reinterpret_cast<uint4*>(C2 + grow * N + gcol) = pk;
            }
            __syncwarp();
        }
    }
}

// ===========================================================================
// Kernel B (wide-N): 128x256x32, 512 thr, 16 warps (2m x 8n) of 64x32.
// Same warps/SMSP hiding as kernel A; half the A L2-traffic per FLOP.
// NT only; bias; optional GELU; fp32 and/or half out.
// ===========================================================================
template<bool DO_GELU, bool OUT_F32, bool OUT_HALF>
__global__ __launch_bounds__(512, 1)
void hgemm_wide(const __half* __restrict__ A, const __half* __restrict__ Bm,
                const float* __restrict__ bias,
                float* __restrict__ C, __half* __restrict__ C2,
                int M, int N, int K)
{
    constexpr int BM = 128, BN = 256, BK = 32;
    constexpr int LDA = 40;     // halves
    constexpr int LDB = 264;    // halves

    __shared__ __half As[2][BM][LDA];
    __shared__ __half Bs[2][BK][LDB];
    __shared__ float  stg[16][16][20];

    const int tid  = threadIdx.x;
    const int wid  = tid / 32;
    const int lane = tid % 32;
    const int warp_m = wid % 2;      // 0..1 -> 64-row slab
    const int warp_n = wid / 2;      // 0..7 -> 32-col slab
    const int cRow = blockIdx.y * BM;
    const int cCol = blockIdx.x * BN;

    const int nT = K / BK;

    const int a_r  = tid >> 2;          // 0..127 (one rep)
    const int a_c  = (tid & 3) * 8;     // 0..24 halves
    const int b_r0 = tid >> 5;          // 0..15, 2 reps stride 16
    const int b_c  = (tid & 31) * 8;    // 0..248 halves

    const __half* Abase = A + (long)(cRow + a_r) * K + a_c;

    {
        cp_async16(&As[0][a_r][a_c], Abase);
#pragma unroll
        for (int i = 0; i < 2; i++)
            cp_async16(&Bs[0][b_r0 + 16 * i][b_c], Bm + (long)(b_r0 + 16 * i) * N + cCol + b_c);
        cp_commit();
    }

    wmma::fragment<wmma::accumulator, 16, 16, 16, float> acc[4][2];
#pragma unroll
    for (int mt = 0; mt < 4; mt++)
#pragma unroll
        for (int nt = 0; nt < 2; nt++)
            wmma::fill_fragment(acc[mt][nt], 0.0f);

    for (int t = 0; t < nT; t++) {
        if (t + 1 < nT) {
            const int kt = (t + 1) * BK;
            const int nb = (t + 1) & 1;
            cp_async16(&As[nb][a_r][a_c], Abase + kt);
#pragma unroll
            for (int i = 0; i < 2; i++)
                cp_async16(&Bs[nb][b_r0 + 16 * i][b_c], Bm + (long)(kt + b_r0 + 16 * i) * N + cCol + b_c);
        }
        cp_commit();
        cp_wait1();
        __syncthreads();

        const int cb = t & 1;
#pragma unroll
        for (int kk = 0; kk < BK; kk += 16) {
            wmma::fragment<wmma::matrix_a, 16, 16, 16, __half, wmma::row_major> af[4];
#pragma unroll
            for (int mt = 0; mt < 4; mt++)
                wmma::load_matrix_sync(af[mt], &As[cb][warp_m * 64 + mt * 16][kk], LDA);
            wmma::fragment<wmma::matrix_b, 16, 16, 16, __half, wmma::row_major> bf[2];
#pragma unroll
            for (int nt = 0; nt < 2; nt++)
                wmma::load_matrix_sync(bf[nt], &Bs[cb][kk][warp_n * 32 + nt * 16], LDB);
#pragma unroll
            for (int mt = 0; mt < 4; mt++)
#pragma unroll
                for (int nt = 0; nt < 2; nt++)
                    wmma::mma_sync(acc[mt][nt], af[mt], bf[nt], acc[mt][nt]);
        }
        __syncthreads();
    }

    const int er  = lane >> 1;
    const int ec0 = (lane & 1) * 8;
#pragma unroll
    for (int mt = 0; mt < 4; mt++) {
#pragma unroll
        for (int nt = 0; nt < 2; nt++) {
            wmma::store_matrix_sync(&stg[wid][0][0], acc[mt][nt], 20, wmma::mem_row_major);
            __syncwarp();
            long grow = cRow + warp_m * 64 + mt * 16 + er;
            long gcol = cCol + warp_n * 32 + nt * 16 + ec0;
            float fv[8];
#pragma unroll
            for (int j = 0; j < 8; j++) {
                float v = stg[wid][er][ec0 + j] + bias[gcol + j];
                if (DO_GELU) v = 0.5f * v * (1.0f + erff(v * 0.70710678118f));
                fv[j] = v;
            }
            if (OUT_F32) {
                float4 v0 = { fv[0], fv[1], fv[2], fv[3] };
                float4 v1 = { fv[4], fv[5], fv[6], fv[7] };
                *reinterpret_cast<float4*>(C + grow * N + gcol)     = v0;
                *reinterpret_cast<float4*>(C + grow * N + gcol + 4) = v1;
            }
            if (OUT_HALF) {
                __half2 h0 = __floats2half2_rn(fv[0], fv[1]);
                __half2 h1 = __floats2half2_rn(fv[2], fv[3]);
                __half2 h2 = __floats2half2_rn(fv[4], fv[5]);
                __half2 h3 = __floats2half2_rn(fv[6], fv[7]);
                uint4 pk;
                pk.x = *reinterpret_cast<unsigned*>(&h0);
                pk.y = *reinterpret_cast<unsigned*>(&h1);
                pk.z = *reinterpret_cast<unsigned*>(&h2);
                pk.w = *reinterpret_cast<unsigned*>(&h3);
                *reinterpret_cast<uint4*>(C2 + grow * N + gcol) = pk;
            }
            __syncwarp();
        }
    }
}

// ---------------------------------------------------------------------------
// Causal row softmax: fp32 scores -> half probs (+ zero fill).
// ---------------------------------------------------------------------------
__global__ void softmax_causal(const float* __restrict__ s, __half* __restrict__ pout) {
    const int row = blockIdx.x;
    const int q   = row % TT;
    const float* p = s + (long)row * TT;
    __half* po = pout + (long)row * TT;
    const int n = q + 1;
    const int tid = threadIdx.x;
    __shared__ float red[256];

    float m = -INFINITY;
    for (int j = tid; j < n; j += 256) m = fmaxf(m, p[j]);
    red[tid] = m; __syncthreads();
    for (int st = 128; st > 0; st >>= 1) {
        if (tid < st) red[tid] = fmaxf(red[tid], red[tid + st]);
        __syncthreads();
    }
    m = red[0]; __syncthreads();

    float sum = 0.f;
    for (int j = tid; j < n; j += 256) sum += __expf(p[j] - m);
    red[tid] = sum; __syncthreads();
    for (int st = 128; st > 0; st >>= 1) {
        if (tid < st) red[tid] += red[tid + st];
        __syncthreads();
    }
    const float inv = 1.0f / red[0];
    __syncthreads();

    for (int j = tid; j < n; j += 256)
        po[j] = __float2half_rn(__expf(p[j] - m) * inv);
    for (int j = n + tid; j < TT; j += 256)
        po[j] = __float2half_rn(0.f);
}

// ---------------------------------------------------------------------------
// Launch
// ---------------------------------------------------------------------------
extern "C" void kernel_launch(void* const* d_in, const int* in_sizes, int n_in,
                              void* d_out, int out_size) {
    const int*   idx  = (const int*)d_in[0];
    const float* tok  = (const float*)d_in[1];
    const float* pos  = (const float*)d_in[2];
    const float* Wq   = (const float*)d_in[3];
    const float* Wk   = (const float*)d_in[4];
    const float* Wv   = (const float*)d_in[5];
    const float* W1   = (const float*)d_in[6];
    const float* b1   = (const float*)d_in[7];
    const float* W2   = (const float*)d_in[8];
    const float* b2   = (const float*)d_in[9];
    const float* Wout = (const float*)d_in[10];
    const float* bout = (const float*)d_in[11];
    float* out = (float*)d_out;

    float  *x, *s;
    __half *xh, *q, *k, *v, *p, *h;
    __half *wq, *wk, *wv, *w1, *w2, *wo;
    cudaGetSymbolAddress((void**)&x,  g_x);
    cudaGetSymbolAddress((void**)&xh, g_xh);
    cudaGetSymbolAddress((void**)&q,  g_q);
    cudaGetSymbolAddress((void**)&k,  g_k);
    cudaGetSymbolAddress((void**)&v,  g_v);
    cudaGetSymbolAddress((void**)&s,  g_s);
    cudaGetSymbolAddress((void**)&p,  g_p);
    cudaGetSymbolAddress((void**)&h,  g_h);
    cudaGetSymbolAddress((void**)&wq, g_wq);
    cudaGetSymbolAddress((void**)&wk, g_wk);
    cudaGetSymbolAddress((void**)&wv, g_wv);
    cudaGetSymbolAddress((void**)&w1, g_w1);
    cudaGetSymbolAddress((void**)&w2, g_w2);
    cudaGetSymbolAddress((void**)&wo, g_wo);

    // 0. convert weights to half
    {
        auto cv = [](const float* in, __half* outp, long n) {
            int n8 = (int)(n / 8);
            f2h_kernel<<<(n8 + 255) / 256, 256>>>(in, outp, n8);
        };
        cv(Wq,   wq, (long)D_MODEL * D_MODEL);
        cv(Wk,   wk, (long)D_MODEL * D_MODEL);
        cv(Wv,   wv, (long)D_MODEL * D_MODEL);
        cv(W1,   w1, (long)D_MODEL * D_FF);
        cv(W2,   w2, (long)D_FF * D_MODEL);
        cv(Wout, wo, (long)D_MODEL * VOCAB);
    }

    // 1. embeddings
    {
        int n4 = (M_TOT * D_MODEL) / 4;
        embed_kernel<<<(n4 + 255) / 256, 256>>>(idx, tok, pos);
    }

    // 2. q,k,v = xh @ W{q,k,v}  (q pre-scaled by 1/32)  [kernel A]
    {
        dim3 grid(D_MODEL / 128, M_TOT / 128, 1);
        hgemm<false,false,false,false,false,false,false,true><<<grid, 256>>>(xh, wq, nullptr, nullptr, nullptr, q,
            M_TOT, D_MODEL, D_MODEL, 1.0f / 32.0f, 0.f, 0, 0, 0, 0);
        hgemm<false,false,false,false,false,false,false,true><<<grid, 256>>>(xh, wk, nullptr, nullptr, nullptr, k,
            M_TOT, D_MODEL, D_MODEL, 1.0f, 0.f, 0, 0, 0, 0);
        hgemm<false,false,false,false,false,false,false,true><<<grid, 256>>>(xh, wv, nullptr, nullptr, nullptr, v,
            M_TOT, D_MODEL, D_MODEL, 1.0f, 0.f, 0, 0, 0, 0);
    }

    // 3. scores = q @ k^T, lower-triangle tiles  [kernel A]
    {
        dim3 grid(TT / 128, TT / 128, BB);
        hgemm<true,false,false,false,true,false,true,false><<<grid, 256>>>(q, k, nullptr, nullptr, s, nullptr,
            TT, TT, D_MODEL, 1.0f, 0.f,
            (long)TT * D_MODEL, (long)TT * D_MODEL, (long)TT * TT, 0);
    }

    // 4. causal softmax -> half probs
    softmax_causal<<<BB * TT, 256>>>(s, p);

    // 5. x = x + 0.125*(p @ v), K capped  [kernel A]
    {
        dim3 grid(D_MODEL / 128, TT / 128, BB);
        hgemm<false,false,false,true,false,true,true,true><<<grid, 256>>>(p, v, nullptr, x, x, xh,
            TT, D_MODEL, TT, 1.0f, 0.125f,
            (long)TT * TT, (long)TT * D_MODEL, (long)TT * D_MODEL, (long)TT * D_MODEL);
    }

    // 6. h = gelu(xh @ W1 + b1)  [wide kernel]
    {
        dim3 grid(D_FF / 256, M_TOT / 128, 1);
        hgemm_wide<true,false,true><<<grid, 512>>>(xh, w1, b1, nullptr, h,
            M_TOT, D_FF, D_MODEL);
    }

    // 7. x = x + (h @ W2 + b2)  [kernel A]
    {
        dim3 grid(D_MODEL / 128, M_TOT / 128, 1);
        hgemm<false,true,false,true,false,false,true,true><<<grid, 256>>>(h, w2, b2, x, x, xh,
            M_TOT, D_MODEL, D_FF, 1.0f, 1.0f, 0, 0, 0, 0);
    }

    // 8. out = xh @ Wout + bout  [wide kernel]
    {
        dim3 grid(VOCAB / 256, M_TOT / 128, 1);
        hgemm_wide<false,true,false><<<grid, 512>>>(xh, wo, bout, out, nullptr,
            M_TOT, VOCAB, D_MODEL);
    }
}

// round 12
// speedup vs baseline: 1.2239x; 1.2239x over previous
#include <cuda_runtime.h>
#include <mma.h>
#include <cuda_fp16.h>
#include <math.h>
#include <stdint.h>

using namespace nvcuda;

#define D_MODEL 1024
#define VOCAB   32000
#define BB      2
#define TT      2048
#define M_TOT   (BB * TT)      // 4096
#define D_FF    (4 * D_MODEL)  // 4096

// ---------------------------------------------------------------------------
// Scratch
// ---------------------------------------------------------------------------
__device__ float  g_x [M_TOT * D_MODEL];
__device__ __half g_xh[M_TOT * D_MODEL];
__device__ __half g_q [M_TOT * D_MODEL];   // q pre-scaled by 1/32
__device__ __half g_k [M_TOT * D_MODEL];
__device__ __half g_v [M_TOT * D_MODEL];
__device__ float  g_s [BB * TT * TT];
__device__ __half g_p [BB * TT * TT];
__device__ __half g_h [M_TOT * D_FF];
__device__ __half g_wq[D_MODEL * D_MODEL];
__device__ __half g_wk[D_MODEL * D_MODEL];
__device__ __half g_wv[D_MODEL * D_MODEL];
__device__ __half g_w1[D_MODEL * D_FF];
__device__ __half g_w2[D_FF * D_MODEL];
__device__ __half g_wo[D_MODEL * VOCAB];

// ---------------------------------------------------------------------------
// helpers
// ---------------------------------------------------------------------------
__device__ __forceinline__ void cp_async16(void* dst, const void* src) {
    unsigned d = (unsigned)__cvta_generic_to_shared(dst);
    asm volatile("cp.async.ca.shared.global [%0], [%1], 16;\n" :: "r"(d), "l"(src));
}
__device__ __forceinline__ void cp_commit() { asm volatile("cp.async.commit_group;\n"); }
__device__ __forceinline__ void cp_wait1()  { asm volatile("cp.async.wait_group 1;\n"); }

__global__ void f2h_kernel(const float* __restrict__ in, __half* __restrict__ out, int n8) {
    int i = blockIdx.x * blockDim.x + threadIdx.x;
    if (i >= n8) return;
    const float4 a = reinterpret_cast<const float4*>(in)[i * 2 + 0];
    const float4 b = reinterpret_cast<const float4*>(in)[i * 2 + 1];
    __half2 h0 = __floats2half2_rn(a.x, a.y);
    __half2 h1 = __floats2half2_rn(a.z, a.w);
    __half2 h2 = __floats2half2_rn(b.x, b.y);
    __half2 h3 = __floats2half2_rn(b.z, b.w);
    uint4 pk;
    pk.x = *reinterpret_cast<unsigned*>(&h0);
    pk.y = *reinterpret_cast<unsigned*>(&h1);
    pk.z = *reinterpret_cast<unsigned*>(&h2);
    pk.w = *reinterpret_cast<unsigned*>(&h3);
    reinterpret_cast<uint4*>(out)[i] = pk;
}

__global__ void embed_kernel(const int* __restrict__ idx,
                             const float* __restrict__ tok,
                             const float* __restrict__ pos) {
    int i = blockIdx.x * blockDim.x + threadIdx.x;
    int n4 = (M_TOT * D_MODEL) / 4;
    if (i >= n4) return;
    int e   = i * 4;
    int row = e / D_MODEL;
    int d   = e % D_MODEL;
    int t   = row % TT;
    int tk  = idx[row];
    const float4 a = *reinterpret_cast<const float4*>(tok + (long)tk * D_MODEL + d);
    const float4 b = *reinterpret_cast<const float4*>(pos + (long)t  * D_MODEL + d);
    float4 o;
    o.x = a.x + b.x; o.y = a.y + b.y; o.z = a.z + b.z; o.w = a.w + b.w;
    *reinterpret_cast<float4*>(g_x + e) = o;
    __half2 h0 = __floats2half2_rn(o.x, o.y);
    __half2 h1 = __floats2half2_rn(o.z, o.w);
    uint2 pk;
    pk.x = *reinterpret_cast<unsigned*>(&h0);
    pk.y = *reinterpret_cast<unsigned*>(&h1);
    *reinterpret_cast<uint2*>(g_xh + e) = pk;
}

// ===========================================================================
// FP16 GEMM (R9 config): 128x128x64, 256 thr, 8 warps 64x32, 2 CTAs/SM.
//   OUT_DIRECT: fp32 out, bias folded into accumulator init, direct
//               store_matrix_sync epilogue (requires alpha==1, no gelu/res).
// ===========================================================================
template<bool TRANSB, bool HAS_BIAS, bool DO_GELU, bool HAS_RES,
         bool CAUSAL, bool KCAP, bool OUT_F32, bool OUT_HALF, bool OUT_DIRECT>
__global__ __launch_bounds__(256, 2)
void hgemm(const __half* __restrict__ A, const __half* __restrict__ Bm,
           const float* __restrict__ bias, const float* __restrict__ Res,
           float* __restrict__ C, __half* __restrict__ C2,
           int M, int N, int K,
           float alpha, float res_scale,
           long sA, long sB, long sC, long sR)
{
    constexpr int BM = 128, BN = 128, BK = 64;
    constexpr int LDA   = 72;
    constexpr int LDB   = TRANSB ? 72 : 136;
    constexpr int BROWS = TRANSB ? BM : BK;

    if (CAUSAL && blockIdx.x > blockIdx.y) return;

    A  += (long)blockIdx.z * sA;
    Bm += (long)blockIdx.z * sB;
    if (OUT_F32 || OUT_DIRECT) C  += (long)blockIdx.z * sC;
    if (OUT_HALF) C2 += (long)blockIdx.z * sC;
    if (HAS_RES)  Res += (long)blockIdx.z * sR;

    __shared__ __half As[2][BM][LDA];
    __shared__ __half Bs[2][BROWS][LDB];
    __shared__ float  stg[8][16][20];   // also used as bias tile in OUT_DIRECT

    const int tid  = threadIdx.x;
    const int wid  = tid / 32;
    const int lane = tid % 32;
    const int warp_m = wid % 2;
    const int warp_n = wid / 2;
    const int cRow = blockIdx.y * BM;
    const int cCol = blockIdx.x * BN;

    const int Keff = KCAP ? (K < cRow + BM ? K : cRow + BM) : K;
    const int nT = Keff / BK;

    const int a_r0 = tid >> 3;
    const int a_c  = (tid & 7) * 8;
    const int b_r0 = tid >> 4;
    const int b_c  = (tid & 15) * 8;

    const __half* Abase = A + (long)cRow * K + a_c;

    {
#pragma unroll
        for (int i = 0; i < 4; i++)
            cp_async16(&As[0][a_r0 + 32 * i][a_c], Abase + (long)(a_r0 + 32 * i) * K);
        if (!TRANSB) {
#pragma unroll
            for (int i = 0; i < 4; i++)
                cp_async16(&Bs[0][b_r0 + 16 * i][b_c], Bm + (long)(b_r0 + 16 * i) * N + cCol + b_c);
        } else {
#pragma unroll
            for (int i = 0; i < 4; i++)
                cp_async16(&Bs[0][a_r0 + 32 * i][a_c], Bm + (long)(cCol + a_r0 + 32 * i) * K + a_c);
        }
        cp_commit();
    }

    wmma::fragment<wmma::accumulator, 16, 16, 16, float> acc[4][2];
    if (OUT_DIRECT) {
        // build 16x128 bias tile (rows identical) in stg, load into acc frags
        float* bt = &stg[0][0][0];               // 2048 floats needed, have 2560
        for (int i = tid; i < 16 * 128; i += 256)
            bt[i] = HAS_BIAS ? bias[cCol + (i & 127)] : 0.0f;
        __syncthreads();
#pragma unroll
        for (int mt = 0; mt < 4; mt++)
#pragma unroll
            for (int nt = 0; nt < 2; nt++)
                wmma::load_matrix_sync(acc[mt][nt],
                    bt + warp_n * 32 + nt * 16, 128, wmma::mem_row_major);
        __syncthreads();
    } else {
#pragma unroll
        for (int mt = 0; mt < 4; mt++)
#pragma unroll
            for (int nt = 0; nt < 2; nt++)
                wmma::fill_fragment(acc[mt][nt], 0.0f);
    }

    for (int t = 0; t < nT; t++) {
        if (t + 1 < nT) {
            const int kt = (t + 1) * BK;
            const int nb = (t + 1) & 1;
#pragma unroll
            for (int i = 0; i < 4; i++)
                cp_async16(&As[nb][a_r0 + 32 * i][a_c], Abase + kt + (long)(a_r0 + 32 * i) * K);
            if (!TRANSB) {
#pragma unroll
                for (int i = 0; i < 4; i++)
                    cp_async16(&Bs[nb][b_r0 + 16 * i][b_c], Bm + (long)(kt + b_r0 + 16 * i) * N + cCol + b_c);
            } else {
#pragma unroll
                for (int i = 0; i < 4; i++)
                    cp_async16(&Bs[nb][a_r0 + 32 * i][a_c], Bm + (long)(cCol + a_r0 + 32 * i) * K + kt + a_c);
            }
        }
        cp_commit();
        cp_wait1();
        __syncthreads();

        const int cb = t & 1;
#pragma unroll
        for (int kk = 0; kk < BK; kk += 16) {
            wmma::fragment<wmma::matrix_a, 16, 16, 16, __half, wmma::row_major> af[4];
#pragma unroll
            for (int mt = 0; mt < 4; mt++)
                wmma::load_matrix_sync(af[mt], &As[cb][warp_m * 64 + mt * 16][kk], LDA);
            if (!TRANSB) {
                wmma::fragment<wmma::matrix_b, 16, 16, 16, __half, wmma::row_major> bf[2];
#pragma unroll
                for (int nt = 0; nt < 2; nt++)
                    wmma::load_matrix_sync(bf[nt], &Bs[cb][kk][warp_n * 32 + nt * 16], LDB);
#pragma unroll
                for (int mt = 0; mt < 4; mt++)
#pragma unroll
                    for (int nt = 0; nt < 2; nt++)
                        wmma::mma_sync(acc[mt][nt], af[mt], bf[nt], acc[mt][nt]);
            } else {
                wmma::fragment<wmma::matrix_b, 16, 16, 16, __half, wmma::col_major> bf[2];
#pragma unroll
                for (int nt = 0; nt < 2; nt++)
                    wmma::load_matrix_sync(bf[nt], &Bs[cb][warp_n * 32 + nt * 16][kk], LDB);
#pragma unroll
                for (int mt = 0; mt < 4; mt++)
#pragma unroll
                    for (int nt = 0; nt < 2; nt++)
                        wmma::mma_sync(acc[mt][nt], af[mt], bf[nt], acc[mt][nt]);
            }
        }
        __syncthreads();
    }

    if (OUT_DIRECT) {
        // direct fp32 stores, no staging
#pragma unroll
        for (int mt = 0; mt < 4; mt++) {
            long grow0 = cRow + warp_m * 64 + mt * 16;
#pragma unroll
            for (int nt = 0; nt < 2; nt++) {
                long gcol0 = cCol + warp_n * 32 + nt * 16;
                wmma::store_matrix_sync(C + grow0 * N + gcol0, acc[mt][nt], N,
                                        wmma::mem_row_major);
            }
        }
        return;
    }

    const int er  = lane >> 1;
    const int ec0 = (lane & 1) * 8;
#pragma unroll
    for (int mt = 0; mt < 4; mt++) {
#pragma unroll
        for (int nt = 0; nt < 2; nt++) {
            wmma::store_matrix_sync(&stg[wid][0][0], acc[mt][nt], 20, wmma::mem_row_major);
            __syncwarp();
            long grow = cRow + warp_m * 64 + mt * 16 + er;
            long gcol = cCol + warp_n * 32 + nt * 16 + ec0;
            float fv[8];
#pragma unroll
            for (int j = 0; j < 8; j++) {
                float v = alpha * stg[wid][er][ec0 + j];
                if (HAS_BIAS) v += bias[gcol + j];
                if (DO_GELU)  v = 0.5f * v * (1.0f + erff(v * 0.70710678118f));
                if (HAS_RES)  v = Res[grow * N + gcol + j] + res_scale * v;
                fv[j] = v;
            }
            if (OUT_F32) {
                float4 v0 = { fv[0], fv[1], fv[2], fv[3] };
                float4 v1 = { fv[4], fv[5], fv[6], fv[7] };
                *reinterpret_cast<float4*>(C + grow * N + gcol)     = v0;
                *reinterpret_cast<float4*>(C + grow * N + gcol + 4) = v1;
            }
            if (OUT_HALF) {
                __half2 h0 = __floats2half2_rn(fv[0], fv[1]);
                __half2 h1 = __floats2half2_rn(fv[2], fv[3]);
                __half2 h2 = __floats2half2_rn(fv[4], fv[5]);
                __half2 h3 = __floats2half2_rn(fv[6], fv[7]);
                uint4 pk;
                pk.x = *reinterpret_cast<unsigned*>(&h0);
                pk.y = *reinterpret_cast<unsigned*>(&h1);
                pk.z = *reinterpret_cast<unsigned*>(&h2);
                pk.w = *reinterpret_cast<unsigned*>(&h3);
                *reinterpret_cast<uint4*>(C2 + grow * N + gcol) = pk;
            }
            __syncwarp();
        }
    }
}

// ---------------------------------------------------------------------------
// Causal row softmax: fp32 scores -> half probs (+ zero fill).
// ---------------------------------------------------------------------------
__global__ void softmax_causal(const float* __restrict__ s, __half* __restrict__ pout) {
    const int row = blockIdx.x;
    const int q   = row % TT;
    const float* p = s + (long)row * TT;
    __half* po = pout + (long)row * TT;
    const int n = q + 1;
    const int tid = threadIdx.x;
    __shared__ float red[256];

    float m = -INFINITY;
    for (int j = tid; j < n; j += 256) m = fmaxf(m, p[j]);
    red[tid] = m; __syncthreads();
    for (int st = 128; st > 0; st >>= 1) {
        if (tid < st) red[tid] = fmaxf(red[tid], red[tid + st]);
        __syncthreads();
    }
    m = red[0]; __syncthreads();

    float sum = 0.f;
    for (int j = tid; j < n; j += 256) sum += __expf(p[j] - m);
    red[tid] = sum; __syncthreads();
    for (int st = 128; st > 0; st >>= 1) {
        if (tid < st) red[tid] += red[tid + st];
        __syncthreads();
    }
    const float inv = 1.0f / red[0];
    __syncthreads();

    for (int j = tid; j < n; j += 256)
        po[j] = __float2half_rn(__expf(p[j] - m) * inv);
    for (int j = n + tid; j < TT; j += 256)
        po[j] = __float2half_rn(0.f);
}

// ---------------------------------------------------------------------------
// Launch
// ---------------------------------------------------------------------------
extern "C" void kernel_launch(void* const* d_in, const int* in_sizes, int n_in,
                              void* d_out, int out_size) {
    const int*   idx  = (const int*)d_in[0];
    const float* tok  = (const float*)d_in[1];
    const float* pos  = (const float*)d_in[2];
    const float* Wq   = (const float*)d_in[3];
    const float* Wk   = (const float*)d_in[4];
    const float* Wv   = (const float*)d_in[5];
    const float* W1   = (const float*)d_in[6];
    const float* b1   = (const float*)d_in[7];
    const float* W2   = (const float*)d_in[8];
    const float* b2   = (const float*)d_in[9];
    const float* Wout = (const float*)d_in[10];
    const float* bout = (const float*)d_in[11];
    float* out = (float*)d_out;

    float  *x, *s;
    __half *xh, *q, *k, *v, *p, *h;
    __half *wq, *wk, *wv, *w1, *w2, *wo;
    cudaGetSymbolAddress((void**)&x,  g_x);
    cudaGetSymbolAddress((void**)&xh, g_xh);
    cudaGetSymbolAddress((void**)&q,  g_q);
    cudaGetSymbolAddress((void**)&k,  g_k);
    cudaGetSymbolAddress((void**)&v,  g_v);
    cudaGetSymbolAddress((void**)&s,  g_s);
    cudaGetSymbolAddress((void**)&p,  g_p);
    cudaGetSymbolAddress((void**)&h,  g_h);
    cudaGetSymbolAddress((void**)&wq, g_wq);
    cudaGetSymbolAddress((void**)&wk, g_wk);
    cudaGetSymbolAddress((void**)&wv, g_wv);
    cudaGetSymbolAddress((void**)&w1, g_w1);
    cudaGetSymbolAddress((void**)&w2, g_w2);
    cudaGetSymbolAddress((void**)&wo, g_wo);

    // 0. convert weights to half
    {
        auto cv = [](const float* in, __half* outp, long n) {
            int n8 = (int)(n / 8);
            f2h_kernel<<<(n8 + 255) / 256, 256>>>(in, outp, n8);
        };
        cv(Wq,   wq, (long)D_MODEL * D_MODEL);
        cv(Wk,   wk, (long)D_MODEL * D_MODEL);
        cv(Wv,   wv, (long)D_MODEL * D_MODEL);
        cv(W1,   w1, (long)D_MODEL * D_FF);
        cv(W2,   w2, (long)D_FF * D_MODEL);
        cv(Wout, wo, (long)D_MODEL * VOCAB);
    }

    // 1. embeddings
    {
        int n4 = (M_TOT * D_MODEL) / 4;
        embed_kernel<<<(n4 + 255) / 256, 256>>>(idx, tok, pos);
    }

    // 2. q,k,v = xh @ W{q,k,v}  (q pre-scaled by 1/32)
    {
        dim3 grid(D_MODEL / 128, M_TOT / 128, 1);
        hgemm<false,false,false,false,false,false,false,true,false><<<grid, 256>>>(xh, wq, nullptr, nullptr, nullptr, q,
            M_TOT, D_MODEL, D_MODEL, 1.0f / 32.0f, 0.f, 0, 0, 0, 0);
        hgemm<false,false,false,false,false,false,false,true,false><<<grid, 256>>>(xh, wk, nullptr, nullptr, nullptr, k,
            M_TOT, D_MODEL, D_MODEL, 1.0f, 0.f, 0, 0, 0, 0);
        hgemm<false,false,false,false,false,false,false,true,false><<<grid, 256>>>(xh, wv, nullptr, nullptr, nullptr, v,
            M_TOT, D_MODEL, D_MODEL, 1.0f, 0.f, 0, 0, 0, 0);
    }

    // 3. scores = q @ k^T, lower-triangle tiles  [direct store]
    {
        dim3 grid(TT / 128, TT / 128, BB);
        hgemm<true,false,false,false,true,false,false,false,true><<<grid, 256>>>(q, k, nullptr, nullptr, s, nullptr,
            TT, TT, D_MODEL, 1.0f, 0.f,
            (long)TT * D_MODEL, (long)TT * D_MODEL, (long)TT * TT, 0);
    }

    // 4. causal softmax -> half probs
    softmax_causal<<<BB * TT, 256>>>(s, p);

    // 5. x = x + 0.125*(p @ v), K capped
    {
        dim3 grid(D_MODEL / 128, TT / 128, BB);
        hgemm<false,false,false,true,false,true,true,true,false><<<grid, 256>>>(p, v, nullptr, x, x, xh,
            TT, D_MODEL, TT, 1.0f, 0.125f,
            (long)TT * TT, (long)TT * D_MODEL, (long)TT * D_MODEL, (long)TT * D_MODEL);
    }

    // 6. h = gelu(xh @ W1 + b1)
    {
        dim3 grid(D_FF / 128, M_TOT / 128, 1);
        hgemm<false,true,true,false,false,false,false,true,false><<<grid, 256>>>(xh, w1, b1, nullptr, nullptr, h,
            M_TOT, D_FF, D_MODEL, 1.0f, 0.f, 0, 0, 0, 0);
    }

    // 7. x = x + (h @ W2 + b2)
    {
        dim3 grid(D_MODEL / 128, M_TOT / 128, 1);
        hgemm<false,true,false,true,false,false,true,true,false><<<grid, 256>>>(h, w2, b2, x, x, xh,
            M_TOT, D_MODEL, D_FF, 1.0f, 1.0f, 0, 0, 0, 0);
    }

    // 8. out = xh @ Wout + bout  [direct store, bias-in-accumulator]
    {
        dim3 grid(VOCAB / 128, M_TOT / 128, 1);
        hgemm<false,true,false,false,false,false,false,false,true><<<grid, 256>>>(xh, wo, bout, nullptr, out, nullptr,
            M_TOT, VOCAB, D_MODEL, 1.0f, 0.f, 0, 0, 0, 0);
    }
}